// round 9
// baseline (speedup 1.0000x reference)
#include <cuda_runtime.h>
#include <cuda_bf16.h>

// Fused gauge-transport: out[b] = expm(0.5*(omega[e]-omega[e]^T)) @ J[b]
// Order-6 Taylor in matvec form (||X|| ~ 0.05 -> err ~1e-11).
//
// Cooperative gather via shared memory. One block = 128 events.
// Gather: lanes in groups of 16 load one event's 256 B contiguously
// -> 4 L1tex wavefronts per LDG.128 warp instruction instead of ~32.
// Compute: one thread per event, X read from smem (stride 17 float4s,
// 17 mod 8 == 1 -> conflict-free 128-bit shared accesses).

#define K 8
#define EV_PER_BLOCK 128
#define F4_PER_EV 16
#define SROW 17   // float4 stride per event in smem (conflict-free, 16B-aligned)

__global__ void __launch_bounds__(EV_PER_BLOCK)
gauge_transport_kernel(const float* __restrict__ omega,
                       const float* __restrict__ J,
                       const int* __restrict__ edge_idx,
                       float* __restrict__ out,
                       int B)
{
    __shared__ int    sidx[EV_PER_BLOCK];
    __shared__ float4 sX[EV_PER_BLOCK * SROW];

    const int tid  = threadIdx.x;
    const int base = blockIdx.x * EV_PER_BLOCK;

    // Stage this block's indices
    if (base + tid < B) sidx[tid] = edge_idx[base + tid];
    __syncthreads();

    const int nvalid = min(EV_PER_BLOCK, B - base);
    const float4* __restrict__ om4 = reinterpret_cast<const float4*>(omega);

    // Cooperative gather: id walks (event, chunk); 16 consecutive lanes
    // cover one event's 16 float4s (256 B contiguous -> 2 lines).
    #pragma unroll
    for (int i = 0; i < F4_PER_EV; i++) {
        int id = i * EV_PER_BLOCK + tid;   // 0 .. 2047
        int ev = id >> 4;
        int ch = id & 15;
        if (ev < nvalid) {
            long long e = (long long)sidx[ev];
            sX[ev * SROW + ch] = om4[(e << 4) + ch];
        }
    }
    __syncthreads();

    const int b = base + tid;
    if (b >= B) return;

    // Read own matrix from smem (16x LDS.128, conflict-free)
    float X[K][K];
    const float4* __restrict__ mx = &sX[tid * SROW];
    #pragma unroll
    for (int i = 0; i < K; i++) {
        float4 a = mx[2 * i];
        float4 c = mx[2 * i + 1];
        X[i][0] = a.x; X[i][1] = a.y; X[i][2] = a.z; X[i][3] = a.w;
        X[i][4] = c.x; X[i][5] = c.y; X[i][6] = c.z; X[i][7] = c.w;
    }

    // Load J[b] (two LDG.128, contiguous per thread)
    const float4* __restrict__ jp =
        reinterpret_cast<const float4*>(J + ((long long)b << 3));
    float4 j0 = jp[0], j1 = jp[1];
    float v[K] = { j0.x, j0.y, j0.z, j0.w, j1.x, j1.y, j1.z, j1.w };

    // Skew-symmetrize in place: X = 0.5*(X - X^T)
    #pragma unroll
    for (int i = 0; i < K; i++) {
        X[i][i] = 0.0f;
        #pragma unroll
        for (int j = i + 1; j < K; j++) {
            float s = 0.5f * (X[i][j] - X[j][i]);
            X[i][j] = s;
            X[j][i] = -s;
        }
    }

    // Taylor: acc = v; t = v; for k: t = (X@t)/(k+1); acc += t;
    float acc[K], t[K];
    #pragma unroll
    for (int i = 0; i < K; i++) { acc[i] = v[i]; t[i] = v[i]; }

    const float invk[6] = { 1.0f, 0.5f, 1.0f / 3.0f, 0.25f, 0.2f, 1.0f / 6.0f };
    #pragma unroll
    for (int k = 0; k < 6; k++) {
        float nt[K];
        #pragma unroll
        for (int i = 0; i < K; i++) {
            float s = X[i][0] * t[0];
            #pragma unroll
            for (int j = 1; j < K; j++) s = fmaf(X[i][j], t[j], s);
            nt[i] = s * invk[k];
        }
        #pragma unroll
        for (int i = 0; i < K; i++) { t[i] = nt[i]; acc[i] += nt[i]; }
    }

    // Store: two STG.128, contiguous per thread
    float4* __restrict__ outp =
        reinterpret_cast<float4*>(out + ((long long)b << 3));
    outp[0] = make_float4(acc[0], acc[1], acc[2], acc[3]);
    outp[1] = make_float4(acc[4], acc[5], acc[6], acc[7]);
}

extern "C" void kernel_launch(void* const* d_in, const int* in_sizes, int n_in,
                              void* d_out, int out_size)
{
    const float* omega    = (const float*)d_in[0];   // (E, 8, 8) float32
    const float* J        = (const float*)d_in[1];   // (B, 8)    float32
    const int*   edge_idx = (const int*)d_in[2];     // (B,)      int32
    // d_in[3] = edges (E,2) — unused by the reference computation

    float* out = (float*)d_out;
    int B = in_sizes[2];

    int blocks = (B + EV_PER_BLOCK - 1) / EV_PER_BLOCK;
    gauge_transport_kernel<<<blocks, EV_PER_BLOCK>>>(omega, J, edge_idx, out, B);
}

// round 10
// speedup vs baseline: 1.6146x; 1.6146x over previous
#include <cuda_runtime.h>
#include <cuda_bf16.h>

// Fused gauge-transport: out[b] = expm(0.5*(omega[e]-omega[e]^T)) @ J[b]
// Order-4 Taylor in matvec form (||X|| <= ~0.08 -> trunc err ~1.4e-8).
//
// R10: warp-local staged gather (no block barrier).
//  - Each warp stages its own 32 events' matrices into smem:
//    16 LDG.128/thread, instruction i covers events {2i,2i+1} contiguously
//    -> 4 L1tex wavefronts/instr = 2 line-touches/event (vs 16 in R4).
//  - Index broadcast via __shfl_sync (no smem, no extra latency chain).
//  - __syncwarp only: a warp's compute waits on its OWN loads, never on
//    other warps (fixes R9's block-barrier latency collapse).
//  - Compute: one thread per event (R4-proven), X via conflict-free
//    stride-17-float4 LDS.128.

#define K 8
#define SROW 17            // float4 stride per event in smem (conflict-free)
#define WARPS_PER_BLOCK 4
#define THREADS (WARPS_PER_BLOCK * 32)

__global__ void __launch_bounds__(THREADS)
gauge_transport_kernel(const float* __restrict__ omega,
                       const float* __restrict__ J,
                       const int* __restrict__ edge_idx,
                       float* __restrict__ out,
                       int B)
{
    __shared__ float4 sX[WARPS_PER_BLOCK][32 * SROW];

    const int lane = threadIdx.x & 31;
    const int wid  = threadIdx.x >> 5;
    const long long b = (long long)blockIdx.x * THREADS + threadIdx.x;

    // Per-lane index load (coalesced); garbage-safe fallback for tail.
    int my_e = 0;
    if (b < B) my_e = edge_idx[b];

    // Warp-local cooperative gather: instruction i loads events {2i, 2i+1},
    // 16 consecutive lanes walk one event's 256 B contiguously (2 lines).
    float4* __restrict__ sw = sX[wid];
    const float4* __restrict__ om4 = reinterpret_cast<const float4*>(omega);
    #pragma unroll
    for (int i = 0; i < 16; i++) {
        int ev = 2 * i + (lane >> 4);
        int ch = lane & 15;
        long long e = (long long)__shfl_sync(0xffffffffu, my_e, ev);
        sw[ev * SROW + ch] = om4[(e << 4) + ch];
    }
    __syncwarp();

    if (b >= B) return;

    // Read own matrix: 16x LDS.128, stride 17 f4 -> conflict-free.
    float X[K][K];
    const float4* __restrict__ mx = &sw[lane * SROW];
    #pragma unroll
    for (int i = 0; i < K; i++) {
        float4 a = mx[2 * i];
        float4 c = mx[2 * i + 1];
        X[i][0] = a.x; X[i][1] = a.y; X[i][2] = a.z; X[i][3] = a.w;
        X[i][4] = c.x; X[i][5] = c.y; X[i][6] = c.z; X[i][7] = c.w;
    }

    // Load J[b] (two LDG.128, contiguous per thread)
    const float4* __restrict__ jp =
        reinterpret_cast<const float4*>(J + (b << 3));
    float4 j0 = jp[0], j1 = jp[1];
    float v[K] = { j0.x, j0.y, j0.z, j0.w, j1.x, j1.y, j1.z, j1.w };

    // Skew-symmetrize in place: X = 0.5*(X - X^T)
    #pragma unroll
    for (int i = 0; i < K; i++) {
        X[i][i] = 0.0f;
        #pragma unroll
        for (int j = i + 1; j < K; j++) {
            float s = 0.5f * (X[i][j] - X[j][i]);
            X[i][j] = s;
            X[j][i] = -s;
        }
    }

    // Order-4 Taylor: acc = v; t = v; for k: t = (X@t)/(k+1); acc += t;
    float acc[K], t[K];
    #pragma unroll
    for (int i = 0; i < K; i++) { acc[i] = v[i]; t[i] = v[i]; }

    const float invk[4] = { 1.0f, 0.5f, 1.0f / 3.0f, 0.25f };
    #pragma unroll
    for (int k = 0; k < 4; k++) {
        float nt[K];
        #pragma unroll
        for (int i = 0; i < K; i++) {
            float s = X[i][0] * t[0];
            #pragma unroll
            for (int j = 1; j < K; j++) s = fmaf(X[i][j], t[j], s);
            nt[i] = s * invk[k];
        }
        #pragma unroll
        for (int i = 0; i < K; i++) { t[i] = nt[i]; acc[i] += nt[i]; }
    }

    // Store: two STG.128, contiguous per thread
    float4* __restrict__ outp = reinterpret_cast<float4*>(out + (b << 3));
    outp[0] = make_float4(acc[0], acc[1], acc[2], acc[3]);
    outp[1] = make_float4(acc[4], acc[5], acc[6], acc[7]);
}

extern "C" void kernel_launch(void* const* d_in, const int* in_sizes, int n_in,
                              void* d_out, int out_size)
{
    const float* omega    = (const float*)d_in[0];   // (E, 8, 8) float32
    const float* J        = (const float*)d_in[1];   // (B, 8)    float32
    const int*   edge_idx = (const int*)d_in[2];     // (B,)      int32
    // d_in[3] = edges (E,2) — unused by the reference computation

    float* out = (float*)d_out;
    int B = in_sizes[2];

    int blocks = (B + THREADS - 1) / THREADS;
    gauge_transport_kernel<<<blocks, THREADS>>>(omega, J, edge_idx, out, B);
}